// round 7
// baseline (speedup 1.0000x reference)
#include <cuda_runtime.h>
#include <cuda_bf16.h>
#include <cstdint>

// fid[p] = clip( (va.vb)^2 / (|va|^2 |vb|^2), 0, 1 )
// va = tanh( relu(xa @ W1 + b1) @ W2 + b2 )   (quantum circuit is unitary -> cancels)
// GEMM1 via mma.sync m16n8k16 bf16 split hi/lo (3 MMAs). 8 warps, 64x32 warp tiles, M=256/block.
// W1 pre-converted to K-major bf16 hi/lo by prepass; B staged with cp.async; A staged STS.128.

#define KDIM   784
#define KC     16
#define NCHUNK 49
#define ASTR   24      // uint16 elems per smem row (48 B): conflict-free frags + STS.128 staging
#define HSTR   65
#define VSTR   20      // 16B-aligned float4 stores, conflict-free reads

// dynamic smem byte offsets
#define OFF_A_HI(b) ((b) * 12288)              // 256 rows * 48 B per buffer
#define OFF_A_LO(b) (24576 + (b) * 12288)
#define OFF_B_HI(b) (49152 + (b) * 3072)       // 64 rows * 48 B per buffer
#define OFF_B_LO(b) (55296 + (b) * 3072)
#define OFF_H    0                              // epilogue overlay: 128*65*4 = 33280
#define OFF_VS   61440                          // 256*20*4 = 20480
#define OFF_SSQ  81920                          // 256*4
#define OFF_W2   82944                          // 64*16*4
#define OFF_B1   87040
#define OFF_B2   87296
#define SMEM_BYTES 87360

__device__ uint16_t g_W1T_hi[64 * KDIM];   // K-major: [n][k]
__device__ uint16_t g_W1T_lo[64 * KDIM];

#define MMA(d, a, b) asm volatile( \
    "mma.sync.aligned.m16n8k16.row.col.f32.bf16.bf16.f32 " \
    "{%0,%1,%2,%3}, {%4,%5,%6,%7}, {%8,%9}, {%0,%1,%2,%3};" \
    : "+f"(d[0]), "+f"(d[1]), "+f"(d[2]), "+f"(d[3]) \
    : "r"(a[0]), "r"(a[1]), "r"(a[2]), "r"(a[3]), "r"(b[0]), "r"(b[1]))

__device__ __forceinline__ uint32_t bf2u(__nv_bfloat162 v) { return *(uint32_t*)&v; }

__device__ __forceinline__ uint32_t hi2(float x, float y, uint32_t& lo) {
    __nv_bfloat162 h = __float22bfloat162_rn(make_float2(x, y));
    __nv_bfloat162 l = __float22bfloat162_rn(make_float2(
        x - __bfloat162float(h.x), y - __bfloat162float(h.y)));
    lo = bf2u(l);
    return bf2u(h);
}

// 8 floats -> 16B hi + 16B lo, one STS.128 each (conflict-free at 48B row stride)
__device__ __forceinline__ void cvst8(float4 a, float4 b, void* hip, void* lop) {
    uint4 h, l;
    h.x = hi2(a.x, a.y, l.x);
    h.y = hi2(a.z, a.w, l.y);
    h.z = hi2(b.x, b.y, l.z);
    h.w = hi2(b.z, b.w, l.w);
    *(uint4*)hip = h;
    *(uint4*)lop = l;
}

__device__ __forceinline__ void cp16(uint32_t dst, const void* src) {
    asm volatile("cp.async.ca.shared.global [%0], [%1], 16;" :: "r"(dst), "l"(src));
}

__global__ void prep_w1(const float* __restrict__ W1) {
    int i = blockIdx.x * 256 + threadIdx.x;        // 12544 = 64 * 196
    int n  = i / 196;
    int k4 = (i - n * 196) * 4;
    uint32_t h0, h1, l0, l1;
    {
        float v0 = W1[(size_t)(k4 + 0) * 64 + n];
        float v1 = W1[(size_t)(k4 + 1) * 64 + n];
        float v2 = W1[(size_t)(k4 + 2) * 64 + n];
        float v3 = W1[(size_t)(k4 + 3) * 64 + n];
        h0 = hi2(v0, v1, l0);
        h1 = hi2(v2, v3, l1);
    }
    *(uint2*)&g_W1T_hi[n * KDIM + k4] = make_uint2(h0, h1);
    *(uint2*)&g_W1T_lo[n * KDIM + k4] = make_uint2(l0, l1);
}

__global__ __launch_bounds__(256, 2)
void qcm_mma(const float* __restrict__ img_a,
             const float* __restrict__ img_b,
             const float* __restrict__ b1,
             const float* __restrict__ W2,
             const float* __restrict__ b2,
             float* __restrict__ out)
{
    extern __shared__ char smem[];
    const uint32_t sb = (uint32_t)__cvta_generic_to_shared(smem);

    float* W2s = (float*)(smem + OFF_W2);
    float* b1s = (float*)(smem + OFF_B1);
    float* b2s = (float*)(smem + OFF_B2);

    const int t    = threadIdx.x;
    const int lane = t & 31;
    const int wid  = t >> 5;
    const int wr   = wid >> 1;        // 0..3 : 64-row band
    const int wc   = wid & 1;         // 0..1 : 32-col half
    const int g    = lane >> 2;
    const int tig  = lane & 3;
    const int p0   = blockIdx.x * 128;   // 128 pairs per block (256 rows)

    // params
    if (t < 64)  b1s[t] = b1[t];
    if (t < 16)  b2s[t] = b2[t];
    #pragma unroll
    for (int i = 0; i < 4; ++i) W2s[t + i * 256] = W2[t + i * 256];

    // staging: thread t owns global row t (a-rows 0..127, b-rows 128..255)
    const float* rowSrc = (t < 128) ? img_a + (size_t)(p0 + t) * KDIM
                                    : img_b + (size_t)(p0 + t - 128) * KDIM;

    // B staging indices (256 cp.async of 16B per chunk: hi then lo)
    const int bhl   = t >> 7;
    const int brem  = t & 127;
    const int bnrow = brem >> 1;
    const int bhalf = brem & 1;
    const uint16_t* bsrc0 = (bhl ? g_W1T_lo : g_W1T_hi) + bnrow * KDIM + bhalf * 8;
    const uint32_t  bdst0 = sb + (bhl ? OFF_B_LO(0) : OFF_B_HI(0)) + bnrow * 48 + bhalf * 16;
    const uint32_t  bbufd = (uint32_t)(OFF_B_HI(1) - OFF_B_HI(0));   // 3072

    float acc[4][4][4];
    #pragma unroll
    for (int mt = 0; mt < 4; ++mt)
        #pragma unroll
        for (int nt = 0; nt < 4; ++nt)
            #pragma unroll
            for (int j = 0; j < 4; ++j) acc[mt][nt][j] = 0.f;

    // ---- prologue: stage chunk 0 ----
    cp16(bdst0, bsrc0);
    asm volatile("cp.async.commit_group;" ::: "memory");
    {
        float4 v0 = *(const float4*)(rowSrc + 0), v1 = *(const float4*)(rowSrc + 4);
        float4 v2 = *(const float4*)(rowSrc + 8), v3 = *(const float4*)(rowSrc + 12);
        cvst8(v0, v1, smem + OFF_A_HI(0) + t * 48,      smem + OFF_A_LO(0) + t * 48);
        cvst8(v2, v3, smem + OFF_A_HI(0) + t * 48 + 16, smem + OFF_A_LO(0) + t * 48 + 16);
    }
    asm volatile("cp.async.wait_group 0;" ::: "memory");
    __syncthreads();

    // ---- mainloop ----
    for (int c = 0; c < NCHUNK; ++c) {
        const int st = c & 1;
        const int nb = st ^ 1;
        const bool more = (c + 1 < NCHUNK);

        float4 p0v, p1v, p2v, p3v;
        if (more) {
            const int k1 = (c + 1) * KC;
            cp16(bdst0 + nb * bbufd, bsrc0 + k1);
            asm volatile("cp.async.commit_group;" ::: "memory");
            p0v = *(const float4*)(rowSrc + k1 + 0);
            p1v = *(const float4*)(rowSrc + k1 + 4);
            p2v = *(const float4*)(rowSrc + k1 + 8);
            p3v = *(const float4*)(rowSrc + k1 + 12);
        }

        const uint16_t* Ah = (const uint16_t*)(smem + OFF_A_HI(st));
        const uint16_t* Al = (const uint16_t*)(smem + OFF_A_LO(st));
        const uint16_t* Bh = (const uint16_t*)(smem + OFF_B_HI(st));
        const uint16_t* Bl = (const uint16_t*)(smem + OFF_B_LO(st));

        uint32_t bh[4][2], bl[4][2];
        #pragma unroll
        for (int nt = 0; nt < 4; ++nt) {
            int bb = (wc * 32 + nt * 8 + g) * ASTR + 2 * tig;
            bh[nt][0] = *(const uint32_t*)&Bh[bb];
            bh[nt][1] = *(const uint32_t*)&Bh[bb + 8];
            bl[nt][0] = *(const uint32_t*)&Bl[bb];
            bl[nt][1] = *(const uint32_t*)&Bl[bb + 8];
        }

        #pragma unroll
        for (int mt = 0; mt < 4; ++mt) {
            int r0 = (wr * 64 + mt * 16 + g) * ASTR + 2 * tig;
            uint32_t ah[4], al[4];
            ah[0] = *(const uint32_t*)&Ah[r0];
            ah[1] = *(const uint32_t*)&Ah[r0 + 8 * ASTR];
            ah[2] = *(const uint32_t*)&Ah[r0 + 8];
            ah[3] = *(const uint32_t*)&Ah[r0 + 8 * ASTR + 8];
            al[0] = *(const uint32_t*)&Al[r0];
            al[1] = *(const uint32_t*)&Al[r0 + 8 * ASTR];
            al[2] = *(const uint32_t*)&Al[r0 + 8];
            al[3] = *(const uint32_t*)&Al[r0 + 8 * ASTR + 8];
            #pragma unroll
            for (int nt = 0; nt < 4; ++nt) {
                MMA(acc[mt][nt], ah, bh[nt]);
                MMA(acc[mt][nt], ah, bl[nt]);
                MMA(acc[mt][nt], al, bh[nt]);
            }
        }

        if (more) {
            cvst8(p0v, p1v, smem + OFF_A_HI(nb) + t * 48,      smem + OFF_A_LO(nb) + t * 48);
            cvst8(p2v, p3v, smem + OFF_A_HI(nb) + t * 48 + 16, smem + OFF_A_LO(nb) + t * 48 + 16);
        }
        asm volatile("cp.async.wait_group 0;" ::: "memory");
        __syncthreads();
    }

    // ---- epilogue: two half-passes of 128 rows through H (overlays mainloop smem) ----
    float* Hs  = (float*)(smem + OFF_H);
    float* Vs  = (float*)(smem + OFF_VS);
    float* SSQ = (float*)(smem + OFF_SSQ);

    #pragma unroll
    for (int h = 0; h < 2; ++h) {
        // scatter relu(acc + b1): pass h covers global rows wr*64 + 32h + [0,32)
        #pragma unroll
        for (int m2 = 0; m2 < 2; ++m2) {
            int mt = 2 * h + m2;
            int lr = wr * 32 + m2 * 16 + g;
            #pragma unroll
            for (int nt = 0; nt < 4; ++nt) {
                int col = wc * 32 + nt * 8 + 2 * tig;
                float bx = b1s[col], by = b1s[col + 1];
                Hs[lr * HSTR + col]           = fmaxf(acc[mt][nt][0] + bx, 0.f);
                Hs[lr * HSTR + col + 1]       = fmaxf(acc[mt][nt][1] + by, 0.f);
                Hs[(lr + 8) * HSTR + col]     = fmaxf(acc[mt][nt][2] + bx, 0.f);
                Hs[(lr + 8) * HSTR + col + 1] = fmaxf(acc[mt][nt][3] + by, 0.f);
            }
        }
        __syncthreads();

        // v = tanh(H @ W2 + b2): 2 threads per local row, 8 outputs each
        {
            int lr   = t >> 1;
            int half = t & 1;
            int gr   = (lr >> 5) * 64 + h * 32 + (lr & 31);
            float s[8];
            float4 bb0 = *(const float4*)&b2s[half * 8];
            float4 bb1 = *(const float4*)&b2s[half * 8 + 4];
            s[0]=bb0.x; s[1]=bb0.y; s[2]=bb0.z; s[3]=bb0.w;
            s[4]=bb1.x; s[5]=bb1.y; s[6]=bb1.z; s[7]=bb1.w;
            #pragma unroll 8
            for (int kk = 0; kk < 64; ++kk) {
                float hh = Hs[lr * HSTR + kk];
                float4 w0 = *(const float4*)&W2s[kk * 16 + half * 8];
                float4 w1 = *(const float4*)&W2s[kk * 16 + half * 8 + 4];
                s[0]+=hh*w0.x; s[1]+=hh*w0.y; s[2]+=hh*w0.z; s[3]+=hh*w0.w;
                s[4]+=hh*w1.x; s[5]+=hh*w1.y; s[6]+=hh*w1.z; s[7]+=hh*w1.w;
            }
            float sq = 0.f;
            #pragma unroll
            for (int j = 0; j < 8; ++j) { s[j] = tanhf(s[j]); sq += s[j] * s[j]; }
            sq += __shfl_xor_sync(0xffffffffu, sq, 1);
            *(float4*)&Vs[gr * VSTR + half * 8]     = make_float4(s[0], s[1], s[2], s[3]);
            *(float4*)&Vs[gr * VSTR + half * 8 + 4] = make_float4(s[4], s[5], s[6], s[7]);
            if (half == 0) SSQ[gr] = sq;
        }
        __syncthreads();
    }

    // ---- fid = (va.vb)^2 / (|va|^2 |vb|^2), clipped ----
    if (t < 128) {
        float d = 0.f;
        #pragma unroll
        for (int j4 = 0; j4 < 4; ++j4) {
            float4 a = *(const float4*)&Vs[t * VSTR + j4 * 4];
            float4 b = *(const float4*)&Vs[(t + 128) * VSTR + j4 * 4];
            d += a.x * b.x + a.y * b.y + a.z * b.z + a.w * b.w;
        }
        float fid = (d * d) / (SSQ[t] * SSQ[t + 128]);
        out[p0 + t] = fminf(fmaxf(fid, 0.f), 1.f);
    }
}

extern "C" void kernel_launch(void* const* d_in, const int* in_sizes, int n_in,
                              void* d_out, int out_size)
{
    const float* img_a = (const float*)d_in[0];
    const float* img_b = (const float*)d_in[1];
    const float* W1    = (const float*)d_in[2];
    const float* b1    = (const float*)d_in[3];
    const float* W2    = (const float*)d_in[4];
    const float* b2    = (const float*)d_in[5];
    // d_in[6] = theta: unused — the circuit is unitary, fidelity is invariant.
    float* out = (float*)d_out;

    cudaFuncSetAttribute(qcm_mma, cudaFuncAttributeMaxDynamicSharedMemorySize, SMEM_BYTES);
    prep_w1<<<49, 256>>>(W1);                       // W1 -> K-major bf16 hi/lo
    int blocks = out_size / 128;                    // 512
    qcm_mma<<<blocks, 256, SMEM_BYTES>>>(img_a, img_b, b1, W2, b2, out);
}

// round 8
// speedup vs baseline: 1.2242x; 1.2242x over previous
#include <cuda_runtime.h>
#include <cuda_bf16.h>
#include <cstdint>

// fid[p] = clip( (va.vb)^2 / (|va|^2 |vb|^2), 0, 1 )
// va = tanh( relu(xa @ W1 + b1) @ W2 + b2 )   (quantum circuit is unitary -> cancels)
// GEMM1 via mma.sync m16n8k16 bf16 split hi/lo (3 MMAs). R4 config (M=128/block, 8 warps,
// 32x32 warp tiles, 1024 blocks) + W1 pre-converted to K-major bf16 hi/lo, staged via cp.async.

#define KDIM   784
#define KC     16
#define NCHUNK 49
#define ASTR   24      // uint16 elems per smem row (48 B): conflict-free frags + staging
#define HSTR   66

__device__ uint16_t g_W1T_hi[64 * KDIM];   // K-major: [n][k]
__device__ uint16_t g_W1T_lo[64 * KDIM];

#define MMA(d, a, b) asm volatile( \
    "mma.sync.aligned.m16n8k16.row.col.f32.bf16.bf16.f32 " \
    "{%0,%1,%2,%3}, {%4,%5,%6,%7}, {%8,%9}, {%0,%1,%2,%3};" \
    : "+f"(d[0]), "+f"(d[1]), "+f"(d[2]), "+f"(d[3]) \
    : "r"(a[0]), "r"(a[1]), "r"(a[2]), "r"(a[3]), "r"(b[0]), "r"(b[1]))

__device__ __forceinline__ uint32_t bf2u(__nv_bfloat162 v) { return *(uint32_t*)&v; }

__device__ __forceinline__ uint32_t hi2(float x, float y, uint32_t& lo) {
    __nv_bfloat162 h = __float22bfloat162_rn(make_float2(x, y));
    __nv_bfloat162 l = __float22bfloat162_rn(make_float2(
        x - __bfloat162float(h.x), y - __bfloat162float(h.y)));
    lo = bf2u(l);
    return bf2u(h);
}

// convert float4 -> 4x(hi,lo) bf16, store 8B hi + 8B lo
__device__ __forceinline__ void cvst4(float4 v, uint16_t* hi, uint16_t* lo) {
    uint2 h, l;
    h.x = hi2(v.x, v.y, l.x);
    h.y = hi2(v.z, v.w, l.y);
    *(uint2*)hi = h;
    *(uint2*)lo = l;
}

__device__ __forceinline__ void cp16(uint32_t dst, const void* src) {
    asm volatile("cp.async.ca.shared.global [%0], [%1], 16;" :: "r"(dst), "l"(src));
}

__global__ void prep_w1(const float* __restrict__ W1) {
    int i = blockIdx.x * 256 + threadIdx.x;        // 12544 = 64 * 196
    int n  = i / 196;
    int k4 = (i - n * 196) * 4;
    uint32_t h0, h1, l0, l1;
    {
        float v0 = W1[(size_t)(k4 + 0) * 64 + n];
        float v1 = W1[(size_t)(k4 + 1) * 64 + n];
        float v2 = W1[(size_t)(k4 + 2) * 64 + n];
        float v3 = W1[(size_t)(k4 + 3) * 64 + n];
        h0 = hi2(v0, v1, l0);
        h1 = hi2(v2, v3, l1);
    }
    *(uint2*)&g_W1T_hi[n * KDIM + k4] = make_uint2(h0, h1);
    *(uint2*)&g_W1T_lo[n * KDIM + k4] = make_uint2(l0, l1);
}

__global__ __launch_bounds__(256)
void qcm_mma(const float* __restrict__ img_a,
             const float* __restrict__ img_b,
             const float* __restrict__ b1,
             const float* __restrict__ W2,
             const float* __restrict__ b2,
             float* __restrict__ out)
{
    __shared__ __align__(16) union {
        struct {
            uint16_t Ahi[2][128 * ASTR];   // 2 x 6144 B
            uint16_t Alo[2][128 * ASTR];
            uint16_t Bhi[2][64 * ASTR];    // 2 x 3072 B
            uint16_t Blo[2][64 * ASTR];
        } m;                               // 36864 B
        struct {
            float H[128 * HSTR];
            float Vs[128 * 16];
            float ssq[128];
        } e;
    } sm;
    __shared__ float W2s[64 * 16];
    __shared__ float b1s[64];
    __shared__ float b2s[16];

    const int t    = threadIdx.x;
    const int lane = t & 31;
    const int wid  = t >> 5;
    const int wr   = wid >> 1;        // 0..3 : 32-row band
    const int wc   = wid & 1;         // 0..1 : 32-col half
    const int g    = lane >> 2;
    const int tig  = lane & 3;
    const int p0   = blockIdx.x * 64; // 64 pairs per block (128 rows)

    // params
    if (t < 64) b1s[t] = b1[t];
    if (t < 16) b2s[t] = b2[t];
    #pragma unroll
    for (int i = 0; i < 4; ++i) W2s[t + i * 256] = W2[t + i * 256];

    // A staging: thread t owns row (t>>1), k-halves of the 16-chunk
    const int arow = t >> 1;
    const int ak   = (t & 1) * 8;
    const float* abase = (arow < 64 ? img_a + (size_t)(p0 + arow) * KDIM
                                    : img_b + (size_t)(p0 + arow - 64) * KDIM);

    // B staging: one 16B cp.async per thread covers hi+lo (64 rows x 32B)
    const int bhl   = t >> 7;
    const int brem  = t & 127;
    const int bn    = brem >> 1;
    const int bhalf = brem & 1;
    const uint16_t* bsrc = (bhl ? g_W1T_lo : g_W1T_hi) + bn * KDIM + bhalf * 8;

    float acc[2][4][4];
    #pragma unroll
    for (int mt = 0; mt < 2; ++mt)
        #pragma unroll
        for (int nt = 0; nt < 4; ++nt)
            #pragma unroll
            for (int j = 0; j < 4; ++j) acc[mt][nt][j] = 0.f;

    // ---- prologue: stage chunk 0 ----
    {
        uint32_t dst = (uint32_t)__cvta_generic_to_shared(
            bhl ? &sm.m.Blo[0][bn * ASTR + bhalf * 8] : &sm.m.Bhi[0][bn * ASTR + bhalf * 8]);
        cp16(dst, bsrc);
        asm volatile("cp.async.commit_group;" ::: "memory");
        float4 v0 = *(const float4*)(abase + ak);
        float4 v1 = *(const float4*)(abase + ak + 4);
        cvst4(v0, &sm.m.Ahi[0][arow * ASTR + ak],     &sm.m.Alo[0][arow * ASTR + ak]);
        cvst4(v1, &sm.m.Ahi[0][arow * ASTR + ak + 4], &sm.m.Alo[0][arow * ASTR + ak + 4]);
        asm volatile("cp.async.wait_group 0;" ::: "memory");
    }
    __syncthreads();

    // ---- mainloop ----
    for (int c = 0; c < NCHUNK; ++c) {
        const int st = c & 1;
        const int nb = st ^ 1;
        const bool more = (c + 1 < NCHUNK);

        float4 va0, va1;
        if (more) {
            const int k1 = (c + 1) * KC;
            uint32_t dst = (uint32_t)__cvta_generic_to_shared(
                bhl ? &sm.m.Blo[nb][bn * ASTR + bhalf * 8] : &sm.m.Bhi[nb][bn * ASTR + bhalf * 8]);
            cp16(dst, bsrc + k1);
            asm volatile("cp.async.commit_group;" ::: "memory");
            va0 = *(const float4*)(abase + k1 + ak);
            va1 = *(const float4*)(abase + k1 + ak + 4);
        }

        const uint16_t* Ah = sm.m.Ahi[st];
        const uint16_t* Al = sm.m.Alo[st];
        const uint16_t* Bh = sm.m.Bhi[st];
        const uint16_t* Bl = sm.m.Blo[st];

        uint32_t bh[4][2], bl[4][2];
        #pragma unroll
        for (int nt = 0; nt < 4; ++nt) {
            int bb = (wc * 32 + nt * 8 + g) * ASTR + 2 * tig;
            bh[nt][0] = *(const uint32_t*)&Bh[bb];
            bh[nt][1] = *(const uint32_t*)&Bh[bb + 8];
            bl[nt][0] = *(const uint32_t*)&Bl[bb];
            bl[nt][1] = *(const uint32_t*)&Bl[bb + 8];
        }

        #pragma unroll
        for (int mt = 0; mt < 2; ++mt) {
            int r0 = (wr * 32 + mt * 16 + g) * ASTR + 2 * tig;
            uint32_t ah[4], al[4];
            ah[0] = *(const uint32_t*)&Ah[r0];
            ah[1] = *(const uint32_t*)&Ah[r0 + 8 * ASTR];
            ah[2] = *(const uint32_t*)&Ah[r0 + 8];
            ah[3] = *(const uint32_t*)&Ah[r0 + 8 * ASTR + 8];
            al[0] = *(const uint32_t*)&Al[r0];
            al[1] = *(const uint32_t*)&Al[r0 + 8 * ASTR];
            al[2] = *(const uint32_t*)&Al[r0 + 8];
            al[3] = *(const uint32_t*)&Al[r0 + 8 * ASTR + 8];
            #pragma unroll
            for (int nt = 0; nt < 4; ++nt) {
                MMA(acc[mt][nt], ah, bh[nt]);
                MMA(acc[mt][nt], ah, bl[nt]);
                MMA(acc[mt][nt], al, bh[nt]);
            }
        }

        if (more) {
            cvst4(va0, &sm.m.Ahi[nb][arow * ASTR + ak],     &sm.m.Alo[nb][arow * ASTR + ak]);
            cvst4(va1, &sm.m.Ahi[nb][arow * ASTR + ak + 4], &sm.m.Alo[nb][arow * ASTR + ak + 4]);
        }
        asm volatile("cp.async.wait_group 0;" ::: "memory");
        __syncthreads();
    }

    // ---- epilogue: H = relu(acc + b1) into smem (fragment layout scatter) ----
    #pragma unroll
    for (int mt = 0; mt < 2; ++mt) {
        #pragma unroll
        for (int nt = 0; nt < 4; ++nt) {
            int row = wr * 32 + mt * 16 + g;
            int col = wc * 32 + nt * 8 + 2 * tig;
            float bx = b1s[col], by = b1s[col + 1];
            *(float2*)&sm.e.H[row * HSTR + col] =
                make_float2(fmaxf(acc[mt][nt][0] + bx, 0.f), fmaxf(acc[mt][nt][1] + by, 0.f));
            *(float2*)&sm.e.H[(row + 8) * HSTR + col] =
                make_float2(fmaxf(acc[mt][nt][2] + bx, 0.f), fmaxf(acc[mt][nt][3] + by, 0.f));
        }
    }
    __syncthreads();

    // ---- v = tanh(H @ W2 + b2): 2 threads per row, 8 outs each ----
    {
        int row  = t >> 1;
        int half = t & 1;
        float s[8];
        float4 bb0 = *(const float4*)&b2s[half * 8];
        float4 bb1 = *(const float4*)&b2s[half * 8 + 4];
        s[0]=bb0.x; s[1]=bb0.y; s[2]=bb0.z; s[3]=bb0.w;
        s[4]=bb1.x; s[5]=bb1.y; s[6]=bb1.z; s[7]=bb1.w;
        #pragma unroll 8
        for (int kk = 0; kk < 64; ++kk) {
            float h = sm.e.H[row * HSTR + kk];
            float4 w0 = *(const float4*)&W2s[kk * 16 + half * 8];
            float4 w1 = *(const float4*)&W2s[kk * 16 + half * 8 + 4];
            s[0]+=h*w0.x; s[1]+=h*w0.y; s[2]+=h*w0.z; s[3]+=h*w0.w;
            s[4]+=h*w1.x; s[5]+=h*w1.y; s[6]+=h*w1.z; s[7]+=h*w1.w;
        }
        float sq = 0.f;
        #pragma unroll
        for (int j = 0; j < 8; ++j) { s[j] = tanhf(s[j]); sq += s[j] * s[j]; }
        sq += __shfl_xor_sync(0xffffffffu, sq, 1);
        *(float4*)&sm.e.Vs[row * 16 + half * 8]     = make_float4(s[0], s[1], s[2], s[3]);
        *(float4*)&sm.e.Vs[row * 16 + half * 8 + 4] = make_float4(s[4], s[5], s[6], s[7]);
        if (half == 0) sm.e.ssq[row] = sq;
    }
    __syncthreads();

    // ---- fid = (va.vb)^2 / (|va|^2 |vb|^2), clipped ----
    if (t < 64) {
        float d = 0.f;
        #pragma unroll
        for (int j4 = 0; j4 < 4; ++j4) {
            float4 a = *(const float4*)&sm.e.Vs[t * 16 + j4 * 4];
            float4 b = *(const float4*)&sm.e.Vs[(t + 64) * 16 + j4 * 4];
            d += a.x * b.x + a.y * b.y + a.z * b.z + a.w * b.w;
        }
        float fid = (d * d) / (sm.e.ssq[t] * sm.e.ssq[t + 64]);
        out[p0 + t] = fminf(fmaxf(fid, 0.f), 1.f);
    }
}

extern "C" void kernel_launch(void* const* d_in, const int* in_sizes, int n_in,
                              void* d_out, int out_size)
{
    const float* img_a = (const float*)d_in[0];
    const float* img_b = (const float*)d_in[1];
    const float* W1    = (const float*)d_in[2];
    const float* b1    = (const float*)d_in[3];
    const float* W2    = (const float*)d_in[4];
    const float* b2    = (const float*)d_in[5];
    // d_in[6] = theta: unused — the circuit is unitary, fidelity is invariant.
    float* out = (float*)d_out;

    prep_w1<<<49, 256>>>(W1);                   // W1 -> K-major bf16 hi/lo
    int blocks = out_size / 64;                 // 1024
    qcm_mma<<<blocks, 256>>>(img_a, img_b, b1, W2, b2, out);
}

// round 9
// speedup vs baseline: 1.3193x; 1.0777x over previous
#include <cuda_runtime.h>
#include <cuda_bf16.h>
#include <cstdint>

// fid[p] = clip( (va.vb)^2 / (|va|^2 |vb|^2), 0, 1 )
// va = tanh( relu(xa @ W1 + b1) @ W2 + b2 )   (quantum circuit is unitary -> cancels)
// GEMM1 via mma.sync m16n8k16 bf16 split hi/lo (3 MMAs). M=128/block, 8 warps, 32x32 tiles,
// 1024 blocks. W1 pre-converted to K-major bf16 hi/lo, staged via cp.async.
// __launch_bounds__(256,3): cap regs at 85 -> 3 blocks/SM (R7 at 88 regs fell to 2 blocks).

#define KDIM   784
#define KC     16
#define NCHUNK 49
#define ASTR   24      // uint16 elems per smem row (48 B): conflict-free frags + staging
#define HSTR   66

__device__ uint16_t g_W1T_hi[64 * KDIM];   // K-major: [n][k]
__device__ uint16_t g_W1T_lo[64 * KDIM];

#define MMA(d, a, b) asm volatile( \
    "mma.sync.aligned.m16n8k16.row.col.f32.bf16.bf16.f32 " \
    "{%0,%1,%2,%3}, {%4,%5,%6,%7}, {%8,%9}, {%0,%1,%2,%3};" \
    : "+f"(d[0]), "+f"(d[1]), "+f"(d[2]), "+f"(d[3]) \
    : "r"(a[0]), "r"(a[1]), "r"(a[2]), "r"(a[3]), "r"(b[0]), "r"(b[1]))

__device__ __forceinline__ uint32_t bf2u(__nv_bfloat162 v) { return *(uint32_t*)&v; }

__device__ __forceinline__ uint32_t hi2(float x, float y, uint32_t& lo) {
    __nv_bfloat162 h = __float22bfloat162_rn(make_float2(x, y));
    __nv_bfloat162 l = __float22bfloat162_rn(make_float2(
        x - __bfloat162float(h.x), y - __bfloat162float(h.y)));
    lo = bf2u(l);
    return bf2u(h);
}

// convert float4 -> 4x(hi,lo) bf16, store 8B hi + 8B lo
__device__ __forceinline__ void cvst4(float4 v, uint16_t* hi, uint16_t* lo) {
    uint2 h, l;
    h.x = hi2(v.x, v.y, l.x);
    h.y = hi2(v.z, v.w, l.y);
    *(uint2*)hi = h;
    *(uint2*)lo = l;
}

__device__ __forceinline__ void cp16(uint32_t dst, const void* src) {
    asm volatile("cp.async.ca.shared.global [%0], [%1], 16;" :: "r"(dst), "l"(src));
}

__global__ void prep_w1(const float* __restrict__ W1) {
    int i = blockIdx.x * 256 + threadIdx.x;        // 12544 = 64 * 196
    int n  = i / 196;
    int k4 = (i - n * 196) * 4;
    uint32_t h0, h1, l0, l1;
    {
        float v0 = W1[(size_t)(k4 + 0) * 64 + n];
        float v1 = W1[(size_t)(k4 + 1) * 64 + n];
        float v2 = W1[(size_t)(k4 + 2) * 64 + n];
        float v3 = W1[(size_t)(k4 + 3) * 64 + n];
        h0 = hi2(v0, v1, l0);
        h1 = hi2(v2, v3, l1);
    }
    *(uint2*)&g_W1T_hi[n * KDIM + k4] = make_uint2(h0, h1);
    *(uint2*)&g_W1T_lo[n * KDIM + k4] = make_uint2(l0, l1);
}

__global__ __launch_bounds__(256, 3)
void qcm_mma(const float* __restrict__ img_a,
             const float* __restrict__ img_b,
             const float* __restrict__ b1,
             const float* __restrict__ W2,
             const float* __restrict__ b2,
             float* __restrict__ out)
{
    __shared__ __align__(16) union {
        struct {
            uint16_t Ahi[2][128 * ASTR];   // 2 x 6144 B
            uint16_t Alo[2][128 * ASTR];
            uint16_t Bhi[2][64 * ASTR];    // 2 x 3072 B
            uint16_t Blo[2][64 * ASTR];
        } m;                               // 36864 B
        struct {
            float H[128 * HSTR];
            float Vs[128 * 16];
            float ssq[128];
        } e;
    } sm;
    __shared__ float W2s[64 * 16];
    __shared__ float b1s[64];
    __shared__ float b2s[16];

    const int t    = threadIdx.x;
    const int lane = t & 31;
    const int wid  = t >> 5;
    const int wr   = wid >> 1;        // 0..3 : 32-row band
    const int wc   = wid & 1;         // 0..1 : 32-col half
    const int g    = lane >> 2;
    const int tig  = lane & 3;
    const int p0   = blockIdx.x * 64; // 64 pairs per block (128 rows)

    // params
    if (t < 64) b1s[t] = b1[t];
    if (t < 16) b2s[t] = b2[t];
    #pragma unroll
    for (int i = 0; i < 4; ++i) W2s[t + i * 256] = W2[t + i * 256];

    // A staging: thread t owns row (t>>1), k-halves of the 16-chunk
    const int arow = t >> 1;
    const int ak   = (t & 1) * 8;
    const float* abase = (arow < 64 ? img_a + (size_t)(p0 + arow) * KDIM
                                    : img_b + (size_t)(p0 + arow - 64) * KDIM);

    // B staging: one 16B cp.async per thread covers hi+lo (64 rows x 32B)
    const int bhl   = t >> 7;
    const int brem  = t & 127;
    const int bn    = brem >> 1;
    const int bhalf = brem & 1;
    const uint16_t* bsrc = (bhl ? g_W1T_lo : g_W1T_hi) + bn * KDIM + bhalf * 8;

    float acc[2][4][4];
    #pragma unroll
    for (int mt = 0; mt < 2; ++mt)
        #pragma unroll
        for (int nt = 0; nt < 4; ++nt)
            #pragma unroll
            for (int j = 0; j < 4; ++j) acc[mt][nt][j] = 0.f;

    // ---- prologue: stage chunk 0 ----
    {
        uint32_t dst = (uint32_t)__cvta_generic_to_shared(
            bhl ? &sm.m.Blo[0][bn * ASTR + bhalf * 8] : &sm.m.Bhi[0][bn * ASTR + bhalf * 8]);
        cp16(dst, bsrc);
        asm volatile("cp.async.commit_group;" ::: "memory");
        float4 v0 = *(const float4*)(abase + ak);
        float4 v1 = *(const float4*)(abase + ak + 4);
        cvst4(v0, &sm.m.Ahi[0][arow * ASTR + ak],     &sm.m.Alo[0][arow * ASTR + ak]);
        cvst4(v1, &sm.m.Ahi[0][arow * ASTR + ak + 4], &sm.m.Alo[0][arow * ASTR + ak + 4]);
        asm volatile("cp.async.wait_group 0;" ::: "memory");
    }
    __syncthreads();

    // ---- mainloop ----
    for (int c = 0; c < NCHUNK; ++c) {
        const int st = c & 1;
        const int nb = st ^ 1;
        const bool more = (c + 1 < NCHUNK);

        float4 va0, va1;
        if (more) {
            const int k1 = (c + 1) * KC;
            uint32_t dst = (uint32_t)__cvta_generic_to_shared(
                bhl ? &sm.m.Blo[nb][bn * ASTR + bhalf * 8] : &sm.m.Bhi[nb][bn * ASTR + bhalf * 8]);
            cp16(dst, bsrc + k1);
            asm volatile("cp.async.commit_group;" ::: "memory");
            va0 = *(const float4*)(abase + k1 + ak);
            va1 = *(const float4*)(abase + k1 + ak + 4);
        }

        const uint16_t* Ah = sm.m.Ahi[st];
        const uint16_t* Al = sm.m.Alo[st];
        const uint16_t* Bh = sm.m.Bhi[st];
        const uint16_t* Bl = sm.m.Blo[st];

        uint32_t bh[4][2], bl[4][2];
        #pragma unroll
        for (int nt = 0; nt < 4; ++nt) {
            int bb = (wc * 32 + nt * 8 + g) * ASTR + 2 * tig;
            bh[nt][0] = *(const uint32_t*)&Bh[bb];
            bh[nt][1] = *(const uint32_t*)&Bh[bb + 8];
            bl[nt][0] = *(const uint32_t*)&Bl[bb];
            bl[nt][1] = *(const uint32_t*)&Bl[bb + 8];
        }

        #pragma unroll
        for (int mt = 0; mt < 2; ++mt) {
            int r0 = (wr * 32 + mt * 16 + g) * ASTR + 2 * tig;
            uint32_t ah[4], al[4];
            ah[0] = *(const uint32_t*)&Ah[r0];
            ah[1] = *(const uint32_t*)&Ah[r0 + 8 * ASTR];
            ah[2] = *(const uint32_t*)&Ah[r0 + 8];
            ah[3] = *(const uint32_t*)&Ah[r0 + 8 * ASTR + 8];
            al[0] = *(const uint32_t*)&Al[r0];
            al[1] = *(const uint32_t*)&Al[r0 + 8 * ASTR];
            al[2] = *(const uint32_t*)&Al[r0 + 8];
            al[3] = *(const uint32_t*)&Al[r0 + 8 * ASTR + 8];
            #pragma unroll
            for (int nt = 0; nt < 4; ++nt) {
                MMA(acc[mt][nt], ah, bh[nt]);
                MMA(acc[mt][nt], ah, bl[nt]);
                MMA(acc[mt][nt], al, bh[nt]);
            }
        }

        if (more) {
            cvst4(va0, &sm.m.Ahi[nb][arow * ASTR + ak],     &sm.m.Alo[nb][arow * ASTR + ak]);
            cvst4(va1, &sm.m.Ahi[nb][arow * ASTR + ak + 4], &sm.m.Alo[nb][arow * ASTR + ak + 4]);
        }
        asm volatile("cp.async.wait_group 0;" ::: "memory");
        __syncthreads();
    }

    // ---- epilogue: H = relu(acc + b1) into smem (fragment layout scatter) ----
    #pragma unroll
    for (int mt = 0; mt < 2; ++mt) {
        #pragma unroll
        for (int nt = 0; nt < 4; ++nt) {
            int row = wr * 32 + mt * 16 + g;
            int col = wc * 32 + nt * 8 + 2 * tig;
            float bx = b1s[col], by = b1s[col + 1];
            *(float2*)&sm.e.H[row * HSTR + col] =
                make_float2(fmaxf(acc[mt][nt][0] + bx, 0.f), fmaxf(acc[mt][nt][1] + by, 0.f));
            *(float2*)&sm.e.H[(row + 8) * HSTR + col] =
                make_float2(fmaxf(acc[mt][nt][2] + bx, 0.f), fmaxf(acc[mt][nt][3] + by, 0.f));
        }
    }
    __syncthreads();

    // ---- v = tanh(H @ W2 + b2): 2 threads per row, 8 outs each ----
    {
        int row  = t >> 1;
        int half = t & 1;
        float s[8];
        float4 bb0 = *(const float4*)&b2s[half * 8];
        float4 bb1 = *(const float4*)&b2s[half * 8 + 4];
        s[0]=bb0.x; s[1]=bb0.y; s[2]=bb0.z; s[3]=bb0.w;
        s[4]=bb1.x; s[5]=bb1.y; s[6]=bb1.z; s[7]=bb1.w;
        #pragma unroll 8
        for (int kk = 0; kk < 64; ++kk) {
            float h = sm.e.H[row * HSTR + kk];
            float4 w0 = *(const float4*)&W2s[kk * 16 + half * 8];
            float4 w1 = *(const float4*)&W2s[kk * 16 + half * 8 + 4];
            s[0]+=h*w0.x; s[1]+=h*w0.y; s[2]+=h*w0.z; s[3]+=h*w0.w;
            s[4]+=h*w1.x; s[5]+=h*w1.y; s[6]+=h*w1.z; s[7]+=h*w1.w;
        }
        float sq = 0.f;
        #pragma unroll
        for (int j = 0; j < 8; ++j) { s[j] = tanhf(s[j]); sq += s[j] * s[j]; }
        sq += __shfl_xor_sync(0xffffffffu, sq, 1);
        *(float4*)&sm.e.Vs[row * 16 + half * 8]     = make_float4(s[0], s[1], s[2], s[3]);
        *(float4*)&sm.e.Vs[row * 16 + half * 8 + 4] = make_float4(s[4], s[5], s[6], s[7]);
        if (half == 0) sm.e.ssq[row] = sq;
    }
    __syncthreads();

    // ---- fid = (va.vb)^2 / (|va|^2 |vb|^2), clipped ----
    if (t < 64) {
        float d = 0.f;
        #pragma unroll
        for (int j4 = 0; j4 < 4; ++j4) {
            float4 a = *(const float4*)&sm.e.Vs[t * 16 + j4 * 4];
            float4 b = *(const float4*)&sm.e.Vs[(t + 64) * 16 + j4 * 4];
            d += a.x * b.x + a.y * b.y + a.z * b.z + a.w * b.w;
        }
        float fid = (d * d) / (sm.e.ssq[t] * sm.e.ssq[t + 64]);
        out[p0 + t] = fminf(fmaxf(fid, 0.f), 1.f);
    }
}

extern "C" void kernel_launch(void* const* d_in, const int* in_sizes, int n_in,
                              void* d_out, int out_size)
{
    const float* img_a = (const float*)d_in[0];
    const float* img_b = (const float*)d_in[1];
    const float* W1    = (const float*)d_in[2];
    const float* b1    = (const float*)d_in[3];
    const float* W2    = (const float*)d_in[4];
    const float* b2    = (const float*)d_in[5];
    // d_in[6] = theta: unused — the circuit is unitary, fidelity is invariant.
    float* out = (float*)d_out;

    prep_w1<<<49, 256>>>(W1);                   // W1 -> K-major bf16 hi/lo
    int blocks = out_size / 64;                 // 1024
    qcm_mma<<<blocks, 256>>>(img_a, img_b, b1, W2, b2, out);
}